// round 7
// baseline (speedup 1.0000x reference)
#include <cuda_runtime.h>
#include <cuda_bf16.h>
#include <math.h>
#include <stdint.h>

#define B 4
#define S 2048
#define E 1024
#define H 16
#define HD 64
#define EPS 1.1920928955078125e-07f

#define BMA 128      // q rows per CTA (attn)
#define BNA 64       // kv cols per tile
#define LDT 72       // smem row stride (bf16 elems) = 144B
#define LDP 40       // proj smem row stride
#define SMEM_ATTN 73728

// ---------------- scratch (__device__ globals; no allocs allowed) -----------
__device__ float g_Qn[B*H*S*HD];   // fp32 head-major (R1-proven prep output)
__device__ float g_Kn[B*H*S*HD];
__device__ __nv_bfloat16 g_Qh[B*H*S*HD], g_Ql[B*H*S*HD];
__device__ __nv_bfloat16 g_Kh[B*H*S*HD], g_Kl[B*H*S*HD];
__device__ __nv_bfloat16 g_Vh[B*H*S*HD], g_Vl[B*H*S*HD];
__device__ __nv_bfloat16 g_Ch[B*S*E],   g_Cl[B*S*E];
__device__ __nv_bfloat16 g_Wh[E*E],     g_Wl[E*E];

// ---------------- helpers ---------------------------------------------------
__device__ __forceinline__ uint32_t sptr(const void* p) {
    return (uint32_t)__cvta_generic_to_shared(p);
}
__device__ __forceinline__ void ldsm4(uint32_t r[4], uint32_t a) {
    asm volatile("ldmatrix.sync.aligned.m8n8.x4.shared.b16 {%0,%1,%2,%3},[%4];"
                 : "=r"(r[0]), "=r"(r[1]), "=r"(r[2]), "=r"(r[3]) : "r"(a));
}
__device__ __forceinline__ void ldsm2(uint32_t r[2], uint32_t a) {
    asm volatile("ldmatrix.sync.aligned.m8n8.x2.shared.b16 {%0,%1},[%2];"
                 : "=r"(r[0]), "=r"(r[1]) : "r"(a));
}
__device__ __forceinline__ void ldsm2t(uint32_t r[2], uint32_t a) {
    asm volatile("ldmatrix.sync.aligned.m8n8.x2.trans.shared.b16 {%0,%1},[%2];"
                 : "=r"(r[0]), "=r"(r[1]) : "r"(a));
}
__device__ __forceinline__ void mma16816(float d[4], const uint32_t a[4], const uint32_t b[2]) {
    asm volatile(
        "mma.sync.aligned.m16n8k16.row.col.f32.bf16.bf16.f32 "
        "{%0,%1,%2,%3},{%4,%5,%6,%7},{%8,%9},{%0,%1,%2,%3};"
        : "+f"(d[0]), "+f"(d[1]), "+f"(d[2]), "+f"(d[3])
        : "r"(a[0]), "r"(a[1]), "r"(a[2]), "r"(a[3]), "r"(b[0]), "r"(b[1]));
}
__device__ __forceinline__ uint32_t packb(__nv_bfloat16 x, __nv_bfloat16 y) {
    __nv_bfloat162 t = __halves2bfloat162(x, y);
    return *reinterpret_cast<uint32_t*>(&t);
}

// ---------------- kernel 1: rmsnorm + rope (EXACT copy of R1-passing) -------
__global__ __launch_bounds__(256) void prep_kernel(
    const float* __restrict__ q, const float* __restrict__ k,
    const float* __restrict__ qw, const float* __restrict__ kw)
{
    int warp = (blockIdx.x * blockDim.x + threadIdx.x) >> 5;
    int lane = threadIdx.x & 31;
    int h  = warp & (H - 1);
    int bs = warp >> 4;            // b*S + s
    int s  = bs & (S - 1);
    int b  = bs >> 11;             // /2048

    int gi = bs * E + h * HD + 2 * lane;
    float2 qv = *reinterpret_cast<const float2*>(q + gi);
    float2 kv = *reinterpret_cast<const float2*>(k + gi);

    double invd = exp2(-(double)lane * 0.4152410118609203); // log2(10000)/32
    float inv_f = (float)invd;
    float ang = (float)s * inv_f;
    float cs = cosf(ang), sn = sinf(ang);

    float w1q = qw[2 * lane], w2q = qw[2 * lane + 1];
    float w1k = kw[2 * lane], w2k = kw[2 * lane + 1];

    float ssq = qv.x * qv.x + qv.y * qv.y;
    float ssk = kv.x * kv.x + kv.y * kv.y;
    #pragma unroll
    for (int off = 16; off; off >>= 1) {
        ssq += __shfl_xor_sync(0xffffffff, ssq, off);
        ssk += __shfl_xor_sync(0xffffffff, ssk, off);
    }
    float rq = rsqrtf(ssq * (1.0f / HD) + EPS);
    float rk = rsqrtf(ssk * (1.0f / HD) + EPS);

    float qx1 = qv.x * rq * w1q, qx2 = qv.y * rq * w2q;
    float kx1 = kv.x * rk * w1k, kx2 = kv.y * rk * w2k;

    float2 qo = make_float2(qx1 * cs - qx2 * sn, qx1 * sn + qx2 * cs);
    float2 ko = make_float2(kx1 * cs - kx2 * sn, kx1 * sn + kx2 * cs);

    int oi = ((b * H + h) * S + s) * HD + 2 * lane;
    *reinterpret_cast<float2*>(g_Qn + oi) = qo;
    *reinterpret_cast<float2*>(g_Kn + oi) = ko;
}

// ---------------- kernel 2a: fp32 Q/K -> bf16 hi/lo (scale folded in Q) -----
__global__ __launch_bounds__(256) void convqk_kernel()
{
    int u = blockIdx.x * 256 + threadIdx.x;   // pair id
    int i = u * 2;
    const float sc = 0.125f * 1.4426950408889634f; // HD^-0.5 * log2(e)
    float2 qv = *reinterpret_cast<const float2*>(g_Qn + i);
    float2 kv = *reinterpret_cast<const float2*>(g_Kn + i);
    qv.x *= sc; qv.y *= sc;

    __nv_bfloat16 q0 = __float2bfloat16_rn(qv.x), q1 = __float2bfloat16_rn(qv.y);
    __nv_bfloat16 k0 = __float2bfloat16_rn(kv.x), k1 = __float2bfloat16_rn(kv.y);
    reinterpret_cast<uint32_t*>(g_Qh)[u] = packb(q0, q1);
    reinterpret_cast<uint32_t*>(g_Kh)[u] = packb(k0, k1);
    reinterpret_cast<uint32_t*>(g_Ql)[u] = packb(
        __float2bfloat16_rn(qv.x - __bfloat162float(q0)),
        __float2bfloat16_rn(qv.y - __bfloat162float(q1)));
    reinterpret_cast<uint32_t*>(g_Kl)[u] = packb(
        __float2bfloat16_rn(kv.x - __bfloat162float(k0)),
        __float2bfloat16_rn(kv.y - __bfloat162float(k1)));
}

// ---------------- kernel 2b: v [b,s,e] -> head-major bf16 hi/lo -------------
__global__ __launch_bounds__(256) void convv_kernel(const float* __restrict__ v)
{
    int u = blockIdx.x * 256 + threadIdx.x;   // pair id (head-major)
    int i = u * 2;
    int d  = i & (HD - 1);
    int s  = (i >> 6) & (S - 1);
    int bh = i >> 17;
    int h = bh & (H - 1), b = bh >> 4;
    float2 vv = *reinterpret_cast<const float2*>(
        v + (size_t)(b * S + s) * E + h * HD + d);
    __nv_bfloat16 v0 = __float2bfloat16_rn(vv.x), v1 = __float2bfloat16_rn(vv.y);
    reinterpret_cast<uint32_t*>(g_Vh)[u] = packb(v0, v1);
    reinterpret_cast<uint32_t*>(g_Vl)[u] = packb(
        __float2bfloat16_rn(vv.x - __bfloat162float(v0)),
        __float2bfloat16_rn(vv.y - __bfloat162float(v1)));
}

// ---------------- kernel 2c: W -> bf16 hi/lo --------------------------------
__global__ void wconv_kernel(const float* __restrict__ W) {
    int i = blockIdx.x * 256 + threadIdx.x;
    float x = W[i];
    __nv_bfloat16 hi = __float2bfloat16_rn(x);
    g_Wh[i] = hi;
    g_Wl[i] = __float2bfloat16_rn(x - __bfloat162float(hi));
}

// ---------------- kernel 3: flash attention (bf16x3 mma + ldmatrix) ---------
// 256 threads = 8 warps; warp w owns rows [16w,16w+16) of a 128-row q tile.
__global__ __launch_bounds__(256) void attn_kernel()
{
    extern __shared__ __nv_bfloat16 smb[];
    __nv_bfloat16* sQh = smb;              // [128][LDT]
    __nv_bfloat16* sQl = smb + 9216;
    __nv_bfloat16* sKh = smb + 18432;      // [64][LDT]  (row kv, col d)
    __nv_bfloat16* sKl = smb + 23040;
    __nv_bfloat16* sVh = smb + 27648;      // [64][LDT]  (row kv, col d)
    __nv_bfloat16* sVl = smb + 32256;

    int bh = blockIdx.y, qt = blockIdx.x;
    int tid = threadIdx.x, w = tid >> 5, t = tid & 31;
    int gid = t >> 2, tig = t & 3;
    int w16 = w * 16;

    size_t base = (size_t)bh * S * HD;
    const __nv_bfloat16* Qhb = g_Qh + base + (size_t)qt * BMA * HD;
    const __nv_bfloat16* Qlb = g_Ql + base + (size_t)qt * BMA * HD;
    const __nv_bfloat16* Khb = g_Kh + base;
    const __nv_bfloat16* Klb = g_Kl + base;
    const __nv_bfloat16* Vhb = g_Vh + base;
    const __nv_bfloat16* Vlb = g_Vl + base;

    // load Q tile (hi/lo): 128 rows x 64 elems
    #pragma unroll
    for (int i = 0; i < 4; i++) {
        int lin = i * 256 + tid;
        int r = lin >> 3, c = lin & 7;
        *reinterpret_cast<uint4*>(sQh + r * LDT + c * 8) =
            *reinterpret_cast<const uint4*>(Qhb + r * HD + c * 8);
        *reinterpret_cast<uint4*>(sQl + r * LDT + c * 8) =
            *reinterpret_cast<const uint4*>(Qlb + r * HD + c * 8);
    }

    float accO[8][4];
    #pragma unroll
    for (int j = 0; j < 8; j++)
        #pragma unroll
        for (int c = 0; c < 4; c++) accO[j][c] = 0.f;
    float m0 = -1e30f, m1 = -1e30f, l0 = 0.f, l1 = 0.f;

    // ldmatrix base addresses (layouts re-derived vs PTX fragment tables)
    uint32_t aQh = sptr(sQh + (w16 + (t & 15)) * LDT + (t >> 4) * 8);
    uint32_t aQl = sptr(sQl + (w16 + (t & 15)) * LDT + (t >> 4) * 8);
    uint32_t aKh = sptr(sKh + (t & 7) * LDT + ((t >> 3) & 1) * 8);
    uint32_t aKl = sptr(sKl + (t & 7) * LDT + ((t >> 3) & 1) * 8);
    uint32_t aVh = sptr(sVh + (t & 15) * LDT);
    uint32_t aVl = sptr(sVl + (t & 15) * LDT);

    for (int kt = 0; kt < S / BNA; kt++) {
        __syncthreads();
        #pragma unroll
        for (int i = 0; i < 2; i++) {
            int lin = i * 256 + tid;
            int r = lin >> 3, c = lin & 7;
            size_t g = (size_t)(kt * BNA + r) * HD + c * 8;
            int sm = r * LDT + c * 8;
            *reinterpret_cast<uint4*>(sKh + sm) = *reinterpret_cast<const uint4*>(Khb + g);
            *reinterpret_cast<uint4*>(sKl + sm) = *reinterpret_cast<const uint4*>(Klb + g);
            *reinterpret_cast<uint4*>(sVh + sm) = *reinterpret_cast<const uint4*>(Vhb + g);
            *reinterpret_cast<uint4*>(sVl + sm) = *reinterpret_cast<const uint4*>(Vlb + g);
        }
        __syncthreads();

        // ---- S = Q K^T (bf16x3) ----
        float accS[8][4];
        #pragma unroll
        for (int j = 0; j < 8; j++)
            #pragma unroll
            for (int c = 0; c < 4; c++) accS[j][c] = 0.f;

        #pragma unroll
        for (int kk = 0; kk < 4; kk++) {
            uint32_t ah[4], al[4];
            ldsm4(ah, aQh + kk * 32);
            ldsm4(al, aQl + kk * 32);
            #pragma unroll
            for (int j = 0; j < 8; j++) {
                uint32_t bhf[2], blf[2];
                uint32_t off = (uint32_t)(j * 8 * LDT + kk * 16) * 2;
                ldsm2(bhf, aKh + off);
                ldsm2(blf, aKl + off);
                mma16816(accS[j], ah, bhf);
                mma16816(accS[j], ah, blf);
                mma16816(accS[j], al, bhf);
            }
        }

        // ---- online softmax (log2 domain) ----
        float mx0 = -1e30f, mx1 = -1e30f;
        #pragma unroll
        for (int j = 0; j < 8; j++) {
            mx0 = fmaxf(mx0, fmaxf(accS[j][0], accS[j][1]));
            mx1 = fmaxf(mx1, fmaxf(accS[j][2], accS[j][3]));
        }
        #pragma unroll
        for (int off = 1; off <= 2; off <<= 1) {
            mx0 = fmaxf(mx0, __shfl_xor_sync(0xffffffff, mx0, off));
            mx1 = fmaxf(mx1, __shfl_xor_sync(0xffffffff, mx1, off));
        }
        float mn0 = fmaxf(m0, mx0), mn1 = fmaxf(m1, mx1);
        float sc0 = exp2f(m0 - mn0), sc1 = exp2f(m1 - mn1);
        m0 = mn0; m1 = mn1;
        float rs0 = 0.f, rs1 = 0.f;
        #pragma unroll
        for (int j = 0; j < 8; j++) {
            accS[j][0] = exp2f(accS[j][0] - mn0);
            accS[j][1] = exp2f(accS[j][1] - mn0);
            accS[j][2] = exp2f(accS[j][2] - mn1);
            accS[j][3] = exp2f(accS[j][3] - mn1);
            rs0 += accS[j][0] + accS[j][1];
            rs1 += accS[j][2] + accS[j][3];
        }
        #pragma unroll
        for (int off = 1; off <= 2; off <<= 1) {
            rs0 += __shfl_xor_sync(0xffffffff, rs0, off);
            rs1 += __shfl_xor_sync(0xffffffff, rs1, off);
        }
        l0 = l0 * sc0 + rs0;
        l1 = l1 * sc1 + rs1;
        #pragma unroll
        for (int j = 0; j < 8; j++) {
            accO[j][0] *= sc0; accO[j][1] *= sc0;
            accO[j][2] *= sc1; accO[j][3] *= sc1;
        }

        // ---- O += P V (bf16x3, P register-resident as A fragments) ----
        #pragma unroll
        for (int kk = 0; kk < 4; kk++) {
            const float* p0 = accS[2 * kk];
            const float* p1 = accS[2 * kk + 1];
            __nv_bfloat16 h00 = __float2bfloat16_rn(p0[0]);
            __nv_bfloat16 h01 = __float2bfloat16_rn(p0[1]);
            __nv_bfloat16 h02 = __float2bfloat16_rn(p0[2]);
            __nv_bfloat16 h03 = __float2bfloat16_rn(p0[3]);
            __nv_bfloat16 h10 = __float2bfloat16_rn(p1[0]);
            __nv_bfloat16 h11 = __float2bfloat16_rn(p1[1]);
            __nv_bfloat16 h12 = __float2bfloat16_rn(p1[2]);
            __nv_bfloat16 h13 = __float2bfloat16_rn(p1[3]);
            uint32_t pah[4] = { packb(h00, h01), packb(h02, h03),
                                packb(h10, h11), packb(h12, h13) };
            uint32_t pal[4] = {
                packb(__float2bfloat16_rn(p0[0] - __bfloat162float(h00)),
                      __float2bfloat16_rn(p0[1] - __bfloat162float(h01))),
                packb(__float2bfloat16_rn(p0[2] - __bfloat162float(h02)),
                      __float2bfloat16_rn(p0[3] - __bfloat162float(h03))),
                packb(__float2bfloat16_rn(p1[0] - __bfloat162float(h10)),
                      __float2bfloat16_rn(p1[1] - __bfloat162float(h11))),
                packb(__float2bfloat16_rn(p1[2] - __bfloat162float(h12)),
                      __float2bfloat16_rn(p1[3] - __bfloat162float(h13))) };
            #pragma unroll
            for (int j = 0; j < 8; j++) {
                uint32_t vbh[2], vbl[2];
                uint32_t off = (uint32_t)(kk * 16 * LDT + j * 8) * 2;
                ldsm2t(vbh, aVh + off);
                ldsm2t(vbl, aVl + off);
                mma16816(accO[j], pah, vbh);
                mma16816(accO[j], pah, vbl);
                mma16816(accO[j], pal, vbh);
            }
        }
    }

    // ---- epilogue: normalize, split to bf16 hi/lo ctx ----
    int b = bh >> 4, h = bh & 15;
    float i0 = 1.0f / l0, i1 = 1.0f / l1;
    int row0 = b * S + qt * BMA + w16 + gid;
    int row1 = row0 + 8;
    #pragma unroll
    for (int j = 0; j < 8; j++) {
        int col = h * HD + j * 8 + 2 * tig;
        float x0 = accO[j][0] * i0, x1 = accO[j][1] * i0;
        float x2 = accO[j][2] * i1, x3 = accO[j][3] * i1;
        __nv_bfloat16 a0 = __float2bfloat16_rn(x0), a1 = __float2bfloat16_rn(x1);
        __nv_bfloat16 a2 = __float2bfloat16_rn(x2), a3 = __float2bfloat16_rn(x3);
        size_t u0 = ((size_t)row0 * E + col) >> 1;
        size_t u1 = ((size_t)row1 * E + col) >> 1;
        reinterpret_cast<uint32_t*>(g_Ch)[u0] = packb(a0, a1);
        reinterpret_cast<uint32_t*>(g_Ch)[u1] = packb(a2, a3);
        reinterpret_cast<uint32_t*>(g_Cl)[u0] = packb(
            __float2bfloat16_rn(x0 - __bfloat162float(a0)),
            __float2bfloat16_rn(x1 - __bfloat162float(a1)));
        reinterpret_cast<uint32_t*>(g_Cl)[u1] = packb(
            __float2bfloat16_rn(x2 - __bfloat162float(a2)),
            __float2bfloat16_rn(x3 - __bfloat162float(a3)));
    }
}

// ---------------- kernel 4: projection (bf16x3 mma) -------------------------
// out[m][n] = sum_k ctx[m][k] * W[n][k] + bias[n]; tile 128x64, K-step 32.
__global__ __launch_bounds__(256) void proj_kernel(
    const float* __restrict__ bias, float* __restrict__ out)
{
    __shared__ __nv_bfloat16 sAh[128 * LDP], sAl[128 * LDP];
    __shared__ __nv_bfloat16 sBh[64 * LDP],  sBl[64 * LDP];

    int tid = threadIdx.x, w = tid >> 5, t = tid & 31;
    int nb = blockIdx.x * 64, mb = blockIdx.y * 128;

    float acc[8][4];
    #pragma unroll
    for (int j = 0; j < 8; j++)
        #pragma unroll
        for (int c = 0; c < 4; c++) acc[j][c] = 0.f;

    uint32_t aAh = sptr(sAh + (w * 16 + (t & 15)) * LDP + (t >> 4) * 8);
    uint32_t aAl = sptr(sAl + (w * 16 + (t & 15)) * LDP + (t >> 4) * 8);
    uint32_t aBh = sptr(sBh + (t & 7) * LDP + ((t >> 3) & 1) * 8);
    uint32_t aBl = sptr(sBl + (t & 7) * LDP + ((t >> 3) & 1) * 8);

    for (int kt = 0; kt < E / 32; kt++) {
        __syncthreads();
        #pragma unroll
        for (int i = 0; i < 2; i++) {
            int lin = i * 256 + tid;
            int r = lin >> 2, c = lin & 3;
            size_t g = (size_t)(mb + r) * E + kt * 32 + c * 8;
            *reinterpret_cast<uint4*>(sAh + r * LDP + c * 8) =
                *reinterpret_cast<const uint4*>(g_Ch + g);
            *reinterpret_cast<uint4*>(sAl + r * LDP + c * 8) =
                *reinterpret_cast<const uint4*>(g_Cl + g);
        }
        {
            int r = tid >> 2, c = tid & 3;
            size_t g = (size_t)(nb + r) * E + kt * 32 + c * 8;
            *reinterpret_cast<uint4*>(sBh + r * LDP + c * 8) =
                *reinterpret_cast<const uint4*>(g_Wh + g);
            *reinterpret_cast<uint4*>(sBl + r * LDP + c * 8) =
                *reinterpret_cast<const uint4*>(g_Wl + g);
        }
        __syncthreads();

        #pragma unroll
        for (int kk = 0; kk < 2; kk++) {
            uint32_t ah[4], al[4];
            ldsm4(ah, aAh + kk * 32);
            ldsm4(al, aAl + kk * 32);
            #pragma unroll
            for (int j = 0; j < 8; j++) {
                uint32_t bhf[2], blf[2];
                uint32_t off = (uint32_t)(j * 8 * LDP + kk * 16) * 2;
                ldsm2(bhf, aBh + off);
                ldsm2(blf, aBl + off);
                mma16816(acc[j], ah, bhf);
                mma16816(acc[j], ah, blf);
                mma16816(acc[j], al, bhf);
            }
        }
    }

    int r0 = mb + w * 16 + (t >> 2), r1 = r0 + 8;
    #pragma unroll
    for (int j = 0; j < 8; j++) {
        int c = nb + j * 8 + 2 * (t & 3);
        float b0 = bias[c], b1 = bias[c + 1];
        float2 o0 = make_float2(acc[j][0] + b0, acc[j][1] + b1);
        float2 o1 = make_float2(acc[j][2] + b0, acc[j][3] + b1);
        *reinterpret_cast<float2*>(out + (size_t)r0 * E + c) = o0;
        *reinterpret_cast<float2*>(out + (size_t)r1 * E + c) = o1;
    }
}

// ---------------------------------------------------------------------------
extern "C" void kernel_launch(void* const* d_in, const int* in_sizes, int n_in,
                              void* d_out, int out_size)
{
    const float* q    = (const float*)d_in[0];
    const float* k    = (const float*)d_in[1];
    const float* v    = (const float*)d_in[2];
    const float* qw   = (const float*)d_in[3];
    const float* kw   = (const float*)d_in[4];
    const float* W    = (const float*)d_in[5];
    const float* bias = (const float*)d_in[6];
    float* out = (float*)d_out;

    cudaFuncSetAttribute(attn_kernel,
                         cudaFuncAttributeMaxDynamicSharedMemorySize, SMEM_ATTN);

    prep_kernel<<<(B * S * H) / 8, 256>>>(q, k, qw, kw);
    convqk_kernel<<<(B * H * S * HD) / 512, 256>>>();
    convv_kernel<<<(B * H * S * HD) / 512, 256>>>(v);
    wconv_kernel<<<(E * E) / 256, 256>>>(W);
    attn_kernel<<<dim3(S / BMA, B * H), 256, SMEM_ATTN>>>();
    proj_kernel<<<dim3(E / 64, (B * S) / 128), 256>>>(bias, out);
}

// round 11
// speedup vs baseline: 1.4733x; 1.4733x over previous
#include <cuda_runtime.h>
#include <cuda_bf16.h>
#include <math.h>
#include <stdint.h>

#define B 4
#define S 2048
#define E 1024
#define H 16
#define HD 64
#define EPS 1.1920928955078125e-07f

#define BMA 128      // q rows per CTA (attn)
#define BNA 64       // kv cols per tile
#define LDT 72       // attn smem row stride (bf16 elems) = 144B, conflict-free
#define LDP 40       // proj smem row stride (bf16 elems) = 80B, conflict-free
#define SMEM_ATTN 73728

// ---------------- scratch (__device__ globals; no allocs allowed) -----------
__device__ float g_Qn[B*H*S*HD];   // fp32 head-major prep output
__device__ float g_Kn[B*H*S*HD];
__device__ __nv_bfloat16 g_Qh[B*H*S*HD], g_Ql[B*H*S*HD];
__device__ __nv_bfloat16 g_Kh[B*H*S*HD], g_Kl[B*H*S*HD];
__device__ __nv_bfloat16 g_Vh[B*H*S*HD], g_Vl[B*H*S*HD];
__device__ __nv_bfloat16 g_Ch[B*S*E],   g_Cl[B*S*E];
__device__ __nv_bfloat16 g_Wh[E*E],     g_Wl[E*E];

// ---------------- helpers ---------------------------------------------------
__device__ __forceinline__ void mma16816(float d[4], const uint32_t a[4], const uint32_t b[2]) {
    asm volatile(
        "mma.sync.aligned.m16n8k16.row.col.f32.bf16.bf16.f32 "
        "{%0,%1,%2,%3},{%4,%5,%6,%7},{%8,%9},{%0,%1,%2,%3};"
        : "+f"(d[0]), "+f"(d[1]), "+f"(d[2]), "+f"(d[3])
        : "r"(a[0]), "r"(a[1]), "r"(a[2]), "r"(a[3]), "r"(b[0]), "r"(b[1]));
}
__device__ __forceinline__ uint32_t packb(__nv_bfloat16 x, __nv_bfloat16 y) {
    __nv_bfloat162 t = __halves2bfloat162(x, y);
    return *reinterpret_cast<uint32_t*>(&t);
}
__device__ __forceinline__ uint32_t lds32(const __nv_bfloat16* p) {
    return *reinterpret_cast<const uint32_t*>(p);
}

// ---------------- kernel 1: rmsnorm + rope (R6 structure, exp2f inv_freq) ---
__global__ __launch_bounds__(256) void prep_kernel(
    const float* __restrict__ q, const float* __restrict__ k,
    const float* __restrict__ qw, const float* __restrict__ kw)
{
    int warp = (blockIdx.x * blockDim.x + threadIdx.x) >> 5;
    int lane = threadIdx.x & 31;
    int h  = warp & (H - 1);
    int bs = warp >> 4;            // b*S + s
    int s  = bs & (S - 1);
    int b  = bs >> 11;             // /2048

    int gi = bs * E + h * HD + 2 * lane;
    float2 qv = *reinterpret_cast<const float2*>(q + gi);
    float2 kv = *reinterpret_cast<const float2*>(k + gi);

    // inv_freq = 10000^(-lane/32) via fast f32 exp2 (was double exp2)
    float inv_f = exp2f(-(float)lane * 0.41524101186092029f);
    float ang = (float)s * inv_f;
    float cs = cosf(ang), sn = sinf(ang);

    float w1q = qw[2 * lane], w2q = qw[2 * lane + 1];
    float w1k = kw[2 * lane], w2k = kw[2 * lane + 1];

    float ssq = qv.x * qv.x + qv.y * qv.y;
    float ssk = kv.x * kv.x + kv.y * kv.y;
    #pragma unroll
    for (int off = 16; off; off >>= 1) {
        ssq += __shfl_xor_sync(0xffffffff, ssq, off);
        ssk += __shfl_xor_sync(0xffffffff, ssk, off);
    }
    float rq = rsqrtf(ssq * (1.0f / HD) + EPS);
    float rk = rsqrtf(ssk * (1.0f / HD) + EPS);

    float qx1 = qv.x * rq * w1q, qx2 = qv.y * rq * w2q;
    float kx1 = kv.x * rk * w1k, kx2 = kv.y * rk * w2k;

    float2 qo = make_float2(qx1 * cs - qx2 * sn, qx1 * sn + qx2 * cs);
    float2 ko = make_float2(kx1 * cs - kx2 * sn, kx1 * sn + kx2 * cs);

    int oi = ((b * H + h) * S + s) * HD + 2 * lane;
    *reinterpret_cast<float2*>(g_Qn + oi) = qo;
    *reinterpret_cast<float2*>(g_Kn + oi) = ko;
}

// ---------------- kernel 2a: fp32 Q/K -> bf16 hi/lo (scale folded in Q) -----
__global__ __launch_bounds__(256) void convqk_kernel()
{
    int u = blockIdx.x * 256 + threadIdx.x;   // pair id
    int i = u * 2;
    const float sc = 0.125f * 1.4426950408889634f; // HD^-0.5 * log2(e)
    float2 qv = *reinterpret_cast<const float2*>(g_Qn + i);
    float2 kv = *reinterpret_cast<const float2*>(g_Kn + i);
    qv.x *= sc; qv.y *= sc;

    __nv_bfloat16 q0 = __float2bfloat16_rn(qv.x), q1 = __float2bfloat16_rn(qv.y);
    __nv_bfloat16 k0 = __float2bfloat16_rn(kv.x), k1 = __float2bfloat16_rn(kv.y);
    reinterpret_cast<uint32_t*>(g_Qh)[u] = packb(q0, q1);
    reinterpret_cast<uint32_t*>(g_Kh)[u] = packb(k0, k1);
    reinterpret_cast<uint32_t*>(g_Ql)[u] = packb(
        __float2bfloat16_rn(qv.x - __bfloat162float(q0)),
        __float2bfloat16_rn(qv.y - __bfloat162float(q1)));
    reinterpret_cast<uint32_t*>(g_Kl)[u] = packb(
        __float2bfloat16_rn(kv.x - __bfloat162float(k0)),
        __float2bfloat16_rn(kv.y - __bfloat162float(k1)));
}

// ---------------- kernel 2b: v [b,s,e] -> head-major bf16 hi/lo -------------
__global__ __launch_bounds__(256) void convv_kernel(const float* __restrict__ v)
{
    int u = blockIdx.x * 256 + threadIdx.x;   // pair id (head-major)
    int i = u * 2;
    int d  = i & (HD - 1);
    int s  = (i >> 6) & (S - 1);
    int bh = i >> 17;
    int h = bh & (H - 1), b = bh >> 4;
    float2 vv = *reinterpret_cast<const float2*>(
        v + (size_t)(b * S + s) * E + h * HD + d);
    __nv_bfloat16 v0 = __float2bfloat16_rn(vv.x), v1 = __float2bfloat16_rn(vv.y);
    reinterpret_cast<uint32_t*>(g_Vh)[u] = packb(v0, v1);
    reinterpret_cast<uint32_t*>(g_Vl)[u] = packb(
        __float2bfloat16_rn(vv.x - __bfloat162float(v0)),
        __float2bfloat16_rn(vv.y - __bfloat162float(v1)));
}

// ---------------- kernel 2c: W -> bf16 hi/lo --------------------------------
__global__ void wconv_kernel(const float* __restrict__ W) {
    int i = blockIdx.x * 256 + threadIdx.x;
    float x = W[i];
    __nv_bfloat16 hi = __float2bfloat16_rn(x);
    g_Wh[i] = hi;
    g_Wl[i] = __float2bfloat16_rn(x - __bfloat162float(hi));
}

// ---------------- kernel 3: flash attention (R6-proven explicit-LDS body) ---
// 256 threads = 8 warps; warp w owns rows [16w,16w+16) of a 128-row q tile.
__global__ __launch_bounds__(256) void attn_kernel()
{
    extern __shared__ __nv_bfloat16 smb[];
    __nv_bfloat16* sQh  = smb;              // [128][LDT]
    __nv_bfloat16* sQl  = smb + 9216;
    __nv_bfloat16* sKh  = smb + 18432;      // [64][LDT]  (row kv, col d)
    __nv_bfloat16* sKl  = smb + 23040;
    __nv_bfloat16* sVth = smb + 27648;      // [64][LDT]  V transposed (row d, col kv)
    __nv_bfloat16* sVtl = smb + 32256;

    int bh = blockIdx.y, qt = blockIdx.x;
    int tid = threadIdx.x, w = tid >> 5, t = tid & 31;
    int gid = t >> 2, tig = t & 3;
    int w16 = w * 16;

    size_t base = (size_t)bh * S * HD;
    const __nv_bfloat16* Qhb = g_Qh + base + (size_t)qt * BMA * HD;
    const __nv_bfloat16* Qlb = g_Ql + base + (size_t)qt * BMA * HD;
    const __nv_bfloat16* Khb = g_Kh + base;
    const __nv_bfloat16* Klb = g_Kl + base;
    const __nv_bfloat16* Vhb = g_Vh + base;
    const __nv_bfloat16* Vlb = g_Vl + base;

    #pragma unroll
    for (int i = 0; i < 4; i++) {
        int lin = i * 256 + tid;
        int r = lin >> 3, c = lin & 7;
        *reinterpret_cast<uint4*>(sQh + r * LDT + c * 8) =
            *reinterpret_cast<const uint4*>(Qhb + r * HD + c * 8);
        *reinterpret_cast<uint4*>(sQl + r * LDT + c * 8) =
            *reinterpret_cast<const uint4*>(Qlb + r * HD + c * 8);
    }

    float accO[8][4];
    #pragma unroll
    for (int j = 0; j < 8; j++)
        #pragma unroll
        for (int c = 0; c < 4; c++) accO[j][c] = 0.f;
    float m0 = -1e30f, m1 = -1e30f, l0 = 0.f, l1 = 0.f;

    for (int kt = 0; kt < S / BNA; kt++) {
        __syncthreads();
        #pragma unroll
        for (int i = 0; i < 2; i++) {
            int lin = i * 256 + tid;
            int r = lin >> 3, c = lin & 7;
            size_t g = (size_t)(kt * BNA + r) * HD + c * 8;
            *reinterpret_cast<uint4*>(sKh + r * LDT + c * 8) =
                *reinterpret_cast<const uint4*>(Khb + g);
            *reinterpret_cast<uint4*>(sKl + r * LDT + c * 8) =
                *reinterpret_cast<const uint4*>(Klb + g);
            uint4 vh = *reinterpret_cast<const uint4*>(Vhb + g);
            uint4 vl = *reinterpret_cast<const uint4*>(Vlb + g);
            const __nv_bfloat16* ph = reinterpret_cast<const __nv_bfloat16*>(&vh);
            const __nv_bfloat16* pl = reinterpret_cast<const __nv_bfloat16*>(&vl);
            #pragma unroll
            for (int jj = 0; jj < 8; jj++) {
                sVth[(c * 8 + jj) * LDT + r] = ph[jj];
                sVtl[(c * 8 + jj) * LDT + r] = pl[jj];
            }
        }
        __syncthreads();

        // ---- S = Q K^T (bf16x3) ----
        float accS[8][4];
        #pragma unroll
        for (int j = 0; j < 8; j++)
            #pragma unroll
            for (int c = 0; c < 4; c++) accS[j][c] = 0.f;

        #pragma unroll
        for (int kk = 0; kk < 4; kk++) {
            int kb = kk * 16 + 2 * tig;
            const __nv_bfloat16* q0h = sQh + (w16 + gid) * LDT + kb;
            const __nv_bfloat16* q0l = sQl + (w16 + gid) * LDT + kb;
            uint32_t ah[4], al[4];
            ah[0] = lds32(q0h);               al[0] = lds32(q0l);
            ah[1] = lds32(q0h + 8 * LDT);     al[1] = lds32(q0l + 8 * LDT);
            ah[2] = lds32(q0h + 8);           al[2] = lds32(q0l + 8);
            ah[3] = lds32(q0h + 8 * LDT + 8); al[3] = lds32(q0l + 8 * LDT + 8);
            #pragma unroll
            for (int j = 0; j < 8; j++) {
                const __nv_bfloat16* kr_h = sKh + (j * 8 + gid) * LDT + kb;
                const __nv_bfloat16* kr_l = sKl + (j * 8 + gid) * LDT + kb;
                uint32_t bhf[2] = { lds32(kr_h), lds32(kr_h + 8) };
                uint32_t blf[2] = { lds32(kr_l), lds32(kr_l + 8) };
                mma16816(accS[j], ah, bhf);
                mma16816(accS[j], ah, blf);
                mma16816(accS[j], al, bhf);
            }
        }

        // ---- online softmax (log2 domain) ----
        float mx0 = -1e30f, mx1 = -1e30f;
        #pragma unroll
        for (int j = 0; j < 8; j++) {
            mx0 = fmaxf(mx0, fmaxf(accS[j][0], accS[j][1]));
            mx1 = fmaxf(mx1, fmaxf(accS[j][2], accS[j][3]));
        }
        #pragma unroll
        for (int off = 1; off <= 2; off <<= 1) {
            mx0 = fmaxf(mx0, __shfl_xor_sync(0xffffffff, mx0, off));
            mx1 = fmaxf(mx1, __shfl_xor_sync(0xffffffff, mx1, off));
        }
        float mn0 = fmaxf(m0, mx0), mn1 = fmaxf(m1, mx1);
        float sc0 = exp2f(m0 - mn0), sc1 = exp2f(m1 - mn1);
        m0 = mn0; m1 = mn1;
        float rs0 = 0.f, rs1 = 0.f;
        #pragma unroll
        for (int j = 0; j < 8; j++) {
            accS[j][0] = exp2f(accS[j][0] - mn0);
            accS[j][1] = exp2f(accS[j][1] - mn0);
            accS[j][2] = exp2f(accS[j][2] - mn1);
            accS[j][3] = exp2f(accS[j][3] - mn1);
            rs0 += accS[j][0] + accS[j][1];
            rs1 += accS[j][2] + accS[j][3];
        }
        #pragma unroll
        for (int off = 1; off <= 2; off <<= 1) {
            rs0 += __shfl_xor_sync(0xffffffff, rs0, off);
            rs1 += __shfl_xor_sync(0xffffffff, rs1, off);
        }
        l0 = l0 * sc0 + rs0;
        l1 = l1 * sc1 + rs1;
        #pragma unroll
        for (int j = 0; j < 8; j++) {
            accO[j][0] *= sc0; accO[j][1] *= sc0;
            accO[j][2] *= sc1; accO[j][3] *= sc1;
        }

        // ---- O += P V (bf16x3, P register-resident as A fragments) ----
        #pragma unroll
        for (int kk = 0; kk < 4; kk++) {
            const float* p0 = accS[2 * kk];
            const float* p1 = accS[2 * kk + 1];
            __nv_bfloat16 h00 = __float2bfloat16_rn(p0[0]);
            __nv_bfloat16 h01 = __float2bfloat16_rn(p0[1]);
            __nv_bfloat16 h02 = __float2bfloat16_rn(p0[2]);
            __nv_bfloat16 h03 = __float2bfloat16_rn(p0[3]);
            __nv_bfloat16 h10 = __float2bfloat16_rn(p1[0]);
            __nv_bfloat16 h11 = __float2bfloat16_rn(p1[1]);
            __nv_bfloat16 h12 = __float2bfloat16_rn(p1[2]);
            __nv_bfloat16 h13 = __float2bfloat16_rn(p1[3]);
            uint32_t pah[4] = { packb(h00, h01), packb(h02, h03),
                                packb(h10, h11), packb(h12, h13) };
            uint32_t pal[4] = {
                packb(__float2bfloat16_rn(p0[0] - __bfloat162float(h00)),
                      __float2bfloat16_rn(p0[1] - __bfloat162float(h01))),
                packb(__float2bfloat16_rn(p0[2] - __bfloat162float(h02)),
                      __float2bfloat16_rn(p0[3] - __bfloat162float(h03))),
                packb(__float2bfloat16_rn(p1[0] - __bfloat162float(h10)),
                      __float2bfloat16_rn(p1[1] - __bfloat162float(h11))),
                packb(__float2bfloat16_rn(p1[2] - __bfloat162float(h12)),
                      __float2bfloat16_rn(p1[3] - __bfloat162float(h13))) };
            int kvb = kk * 16 + 2 * tig;
            #pragma unroll
            for (int j = 0; j < 8; j++) {
                const __nv_bfloat16* vr_h = sVth + (j * 8 + gid) * LDT + kvb;
                const __nv_bfloat16* vr_l = sVtl + (j * 8 + gid) * LDT + kvb;
                uint32_t vbh[2] = { lds32(vr_h), lds32(vr_h + 8) };
                uint32_t vbl[2] = { lds32(vr_l), lds32(vr_l + 8) };
                mma16816(accO[j], pah, vbh);
                mma16816(accO[j], pah, vbl);
                mma16816(accO[j], pal, vbh);
            }
        }
    }

    // ---- epilogue: normalize, split to bf16 hi/lo ctx ----
    int b = bh >> 4, h = bh & 15;
    float i0 = 1.0f / l0, i1 = 1.0f / l1;
    int row0 = b * S + qt * BMA + w16 + gid;
    int row1 = row0 + 8;
    #pragma unroll
    for (int j = 0; j < 8; j++) {
        int col = h * HD + j * 8 + 2 * tig;
        float x0 = accO[j][0] * i0, x1 = accO[j][1] * i0;
        float x2 = accO[j][2] * i1, x3 = accO[j][3] * i1;
        __nv_bfloat16 a0 = __float2bfloat16_rn(x0), a1 = __float2bfloat16_rn(x1);
        __nv_bfloat16 a2 = __float2bfloat16_rn(x2), a3 = __float2bfloat16_rn(x3);
        size_t u0 = ((size_t)row0 * E + col) >> 1;
        size_t u1 = ((size_t)row1 * E + col) >> 1;
        reinterpret_cast<uint32_t*>(g_Ch)[u0] = packb(a0, a1);
        reinterpret_cast<uint32_t*>(g_Ch)[u1] = packb(a2, a3);
        reinterpret_cast<uint32_t*>(g_Cl)[u0] = packb(
            __float2bfloat16_rn(x0 - __bfloat162float(a0)),
            __float2bfloat16_rn(x1 - __bfloat162float(a1)));
        reinterpret_cast<uint32_t*>(g_Cl)[u1] = packb(
            __float2bfloat16_rn(x2 - __bfloat162float(a2)),
            __float2bfloat16_rn(x3 - __bfloat162float(a3)));
    }
}

// ---------------- kernel 4: projection (bf16x3 mma, explicit-LDS frags) -----
// out[m][n] = sum_k ctx[m][k] * W[n][k] + bias[n]; tile 128x64, K-step 32.
__global__ __launch_bounds__(256) void proj_kernel(
    const float* __restrict__ bias, float* __restrict__ out)
{
    __shared__ __nv_bfloat16 sAh[128 * LDP], sAl[128 * LDP];
    __shared__ __nv_bfloat16 sBh[64 * LDP],  sBl[64 * LDP];

    int tid = threadIdx.x, w = tid >> 5, t = tid & 31;
    int gid = t >> 2, tig = t & 3;
    int w16 = w * 16;
    int nb = blockIdx.x * 64, mb = blockIdx.y * 128;

    float acc[8][4];
    #pragma unroll
    for (int j = 0; j < 8; j++)
        #pragma unroll
        for (int c = 0; c < 4; c++) acc[j][c] = 0.f;

    for (int kt = 0; kt < E / 32; kt++) {
        __syncthreads();
        #pragma unroll
        for (int i = 0; i < 2; i++) {
            int lin = i * 256 + tid;
            int r = lin >> 2, c = lin & 3;
            size_t g = (size_t)(mb + r) * E + kt * 32 + c * 8;
            *reinterpret_cast<uint4*>(sAh + r * LDP + c * 8) =
                *reinterpret_cast<const uint4*>(g_Ch + g);
            *reinterpret_cast<uint4*>(sAl + r * LDP + c * 8) =
                *reinterpret_cast<const uint4*>(g_Cl + g);
        }
        {
            int r = tid >> 2, c = tid & 3;
            size_t g = (size_t)(nb + r) * E + kt * 32 + c * 8;
            *reinterpret_cast<uint4*>(sBh + r * LDP + c * 8) =
                *reinterpret_cast<const uint4*>(g_Wh + g);
            *reinterpret_cast<uint4*>(sBl + r * LDP + c * 8) =
                *reinterpret_cast<const uint4*>(g_Wl + g);
        }
        __syncthreads();

        #pragma unroll
        for (int kk = 0; kk < 2; kk++) {
            int kb = kk * 16 + 2 * tig;
            const __nv_bfloat16* a0h = sAh + (w16 + gid) * LDP + kb;
            const __nv_bfloat16* a0l = sAl + (w16 + gid) * LDP + kb;
            uint32_t ah[4], al[4];
            ah[0] = lds32(a0h);               al[0] = lds32(a0l);
            ah[1] = lds32(a0h + 8 * LDP);     al[1] = lds32(a0l + 8 * LDP);
            ah[2] = lds32(a0h + 8);           al[2] = lds32(a0l + 8);
            ah[3] = lds32(a0h + 8 * LDP + 8); al[3] = lds32(a0l + 8 * LDP + 8);
            #pragma unroll
            for (int j = 0; j < 8; j++) {
                const __nv_bfloat16* br_h = sBh + (j * 8 + gid) * LDP + kb;
                const __nv_bfloat16* br_l = sBl + (j * 8 + gid) * LDP + kb;
                uint32_t bhf[2] = { lds32(br_h), lds32(br_h + 8) };
                uint32_t blf[2] = { lds32(br_l), lds32(br_l + 8) };
                mma16816(acc[j], ah, bhf);
                mma16816(acc[j], ah, blf);
                mma16816(acc[j], al, bhf);
            }
        }
    }

    int r0 = mb + w16 + gid, r1 = r0 + 8;
    #pragma unroll
    for (int j = 0; j < 8; j++) {
        int c = nb + j * 8 + 2 * tig;
        float b0 = bias[c], b1 = bias[c + 1];
        float2 o0 = make_float2(acc[j][0] + b0, acc[j][1] + b1);
        float2 o1 = make_float2(acc[j][2] + b0, acc[j][3] + b1);
        *reinterpret_cast<float2*>(out + (size_t)r0 * E + c) = o0;
        *reinterpret_cast<float2*>(out + (size_t)r1 * E + c) = o1;
    }
}

// ---------------------------------------------------------------------------
extern "C" void kernel_launch(void* const* d_in, const int* in_sizes, int n_in,
                              void* d_out, int out_size)
{
    const float* q    = (const float*)d_in[0];
    const float* k    = (const float*)d_in[1];
    const float* v    = (const float*)d_in[2];
    const float* qw   = (const float*)d_in[3];
    const float* kw   = (const float*)d_in[4];
    const float* W    = (const float*)d_in[5];
    const float* bias = (const float*)d_in[6];
    float* out = (float*)d_out;

    cudaFuncSetAttribute(attn_kernel,
                         cudaFuncAttributeMaxDynamicSharedMemorySize, SMEM_ATTN);

    prep_kernel<<<(B * S * H) / 8, 256>>>(q, k, qw, kw);
    convqk_kernel<<<(B * H * S * HD) / 512, 256>>>();
    convv_kernel<<<(B * H * S * HD) / 512, 256>>>(v);
    wconv_kernel<<<(E * E) / 256, 256>>>(W);
    attn_kernel<<<dim3(S / BMA, B * H), 256, SMEM_ATTN>>>();
    proj_kernel<<<dim3(E / 64, (B * S) / 128), 256>>>(bias, out);
}